// round 14
// baseline (speedup 1.0000x reference)
#include <cuda_runtime.h>

// RNN_13855564496941: Euler RNN, T=1024, B=4096, H=50.
// R14 = R12 (best: dual-group 4-col warps) with swapped-pair FFMA2s replaced
//   by scalar FFMAs to eliminate the pair-building MOVs:
//   - P chains (direct act pairs) stay packed f32x2;
//   - Q chains become scalar (Qx,Qy) via fmaf on av.y/.x/.w/.z directly.
//   Per swapped pair: (1 FFMA2 + 2 MOV) -> 2 FFMA (-1 slot, -2 fma rt-cyc).
//   Arithmetic identical to R12 (same IEEE ops) -> bit-identical results.
//   Else: 1024 one-warp CTAs, 2 groups x 2 cols, 50 f32x2 weight regs shared,
//   Jrec@1 folded into bias, non-duplicated act quads (1 LDS.128 per 2 j per
//   group), tanh.approx, one __syncwarp/step, batched sOut flush every 8.

namespace {
constexpr int T_STEPS = 1024;
constexpr int B_DIM   = 4096;
constexpr int H_DIM   = 50;
constexpr int KPAIR   = 25;        // float4 act entries (2 rows each)
constexpr int GRID    = B_DIM / 4; // 1024 CTAs, 4 cols each
constexpr float DT    = 0.1f;
constexpr float OMDT  = 0.9f;
}

__device__ __forceinline__ float2 ffma2(float2 a, float2 b, float2 c) {
    unsigned long long A, B, C, D;
    __builtin_memcpy(&A, &a, 8);
    __builtin_memcpy(&B, &b, 8);
    __builtin_memcpy(&C, &c, 8);
    asm("fma.rn.f32x2 %0, %1, %2, %3;" : "=l"(D) : "l"(A), "l"(B), "l"(C));
    float2 d;
    __builtin_memcpy(&d, &D, 8);
    return d;
}

__device__ __forceinline__ float2 fadd2(float2 a, float2 b) {
    unsigned long long A, B, D;
    __builtin_memcpy(&A, &a, 8);
    __builtin_memcpy(&B, &b, 8);
    asm("add.rn.f32x2 %0, %1, %2;" : "=l"(D) : "l"(A), "l"(B));
    float2 d;
    __builtin_memcpy(&d, &D, 8);
    return d;
}

__device__ __forceinline__ float tanh_fast(float x) {
    float y;
    asm("tanh.approx.f32 %0, %1;" : "=f"(y) : "f"(x));
    return y;
}

__global__ __launch_bounds__(32, 7) void rnn_persist(
    const float* __restrict__ inpt,   // (T, B)
    const float* __restrict__ Jin,    // (H, 1)
    const float* __restrict__ Jrec,   // (H, H)
    const float* __restrict__ Jout,   // (1, H)
    const float* __restrict__ bias,   // (H, 1)
    const float* __restrict__ h0,     // (H, B)
    float* __restrict__ out)          // (T, B)
{
    __shared__ float4 sAct[2][2][32];    // [buf][group][lane], non-duplicated
    __shared__ float2 sOut[8][2][33];    // [slot][group][lane], padded rows

    const int lane = threadIdx.x & 31;
    const int r    = 2 * lane;
    const bool valid = (lane < KPAIR);
    const int gc   = blockIdx.x * 4;     // group A: gc,gc+1; group B: gc+2,gc+3

    // weights + folded bias: bs = dt*bias + dt*Jrec@1 (row sums of w)
    float2 w[H_DIM];
    float2 bs = valid ? make_float2(DT * bias[r], DT * bias[r + 1]) : make_float2(0.f, 0.f);
    #pragma unroll
    for (int j = 0; j < H_DIM; j++) {
        float a = valid ? DT * Jrec[r * H_DIM + j]       : 0.0f;
        float b = valid ? DT * Jrec[(r + 1) * H_DIM + j] : 0.0f;
        w[j] = make_float2(a, b);
        bs = fadd2(bs, w[j]);
    }

    const float2 jin = valid ? make_float2(DT * Jin[r], DT * Jin[r + 1]) : make_float2(0.f, 0.f);
    const float2 jo  = valid ? make_float2(Jout[r],     Jout[r + 1])     : make_float2(0.f, 0.f);

    // state per group: P=(h[r][c0], h[r+1][c1]) packed; Qx=h[r][c1], Qy=h[r+1][c0] scalar
    float2 PA, PB;
    float QAx, QAy, QBx, QBy;
    {
        float4 ra = valid ? *reinterpret_cast<const float4*>(&h0[r * B_DIM + gc])
                          : make_float4(0.f, 0.f, 0.f, 0.f);
        float4 rb = valid ? *reinterpret_cast<const float4*>(&h0[(r + 1) * B_DIM + gc])
                          : make_float4(0.f, 0.f, 0.f, 0.f);
        PA = make_float2(ra.x, rb.y);  QAx = ra.y;  QAy = rb.x;
        PB = make_float2(ra.z, rb.w);  QBx = ra.w;  QBy = rb.z;
    }

    const float* xptr = inpt + gc;
    float4 x4 = *reinterpret_cast<const float4*>(xptr);   // x_0 for all 4 cols
    int p = 0;

    for (int t = 0; t < T_STEPS; t++) {
        float4 x4n = make_float4(0.f, 0.f, 0.f, 0.f);
        if (t + 1 < T_STEPS)
            x4n = *reinterpret_cast<const float4*>(xptr + B_DIM);
        xptr += B_DIM;

        // acts = tanh(h): {a_r_c0, a_r_c1, a_{r+1}_c0, a_{r+1}_c1}
        sAct[p][0][lane] = make_float4(tanh_fast(PA.x), tanh_fast(QAx),
                                       tanh_fast(QAy), tanh_fast(PA.y));
        sAct[p][1][lane] = make_float4(tanh_fast(PB.x), tanh_fast(QBx),
                                       tanh_fast(QBy), tanh_fast(PB.y));

        // base terms (local-only) before the barrier
        const float2 om = make_float2(OMDT, OMDT);
        PA = ffma2(om, PA, ffma2(jin, make_float2(x4.x, x4.y), bs));
        PB = ffma2(om, PB, ffma2(jin, make_float2(x4.z, x4.w), bs));
        QAx = fmaf(OMDT, QAx, fmaf(jin.x, x4.y, bs.x));
        QAy = fmaf(OMDT, QAy, fmaf(jin.y, x4.x, bs.y));
        QBx = fmaf(OMDT, QBx, fmaf(jin.x, x4.w, bs.x));
        QBy = fmaf(OMDT, QBy, fmaf(jin.y, x4.z, bs.y));

        __syncwarp();

        // batched output flush (steps t-8..t-1), 16 lanes: 8 rows x 2 groups
        if ((t & 7) == 0 && t > 0 && lane < 16) {
            int g = lane >> 3, L = lane & 7;
            float2 s0 = sOut[L][g][0];
            float2 s1 = sOut[L][g][1];
            #pragma unroll
            for (int l = 2; l < KPAIR; l += 2) {
                s0 = fadd2(s0, sOut[L][g][l]);
                if (l + 1 < KPAIR) s1 = fadd2(s1, sOut[L][g][l + 1]);
            }
            *reinterpret_cast<float2*>(&out[(t - 8 + L) * B_DIM + gc + 2 * g]) = fadd2(s0, s1);
        }

        // matvec: per k, 2 LDS.128; P packed (direct pairs, no movs),
        // Q scalar (no pair building needed)
        #pragma unroll
        for (int k = 0; k < KPAIR; k++) {
            float4 avA = sAct[p][0][k];
            float4 avB = sAct[p][1][k];
            PA  = ffma2(w[2 * k],     make_float2(avA.x, avA.y), PA);
            PB  = ffma2(w[2 * k],     make_float2(avB.x, avB.y), PB);
            QAx = fmaf(w[2 * k].x, avA.y, QAx);
            QAy = fmaf(w[2 * k].y, avA.x, QAy);
            QBx = fmaf(w[2 * k].x, avB.y, QBx);
            QBy = fmaf(w[2 * k].y, avB.x, QBy);
            PA  = ffma2(w[2 * k + 1], make_float2(avA.z, avA.w), PA);
            PB  = ffma2(w[2 * k + 1], make_float2(avB.z, avB.w), PB);
            QAx = fmaf(w[2 * k + 1].x, avA.w, QAx);
            QAy = fmaf(w[2 * k + 1].y, avA.z, QAy);
            QBx = fmaf(w[2 * k + 1].x, avB.w, QBx);
            QBy = fmaf(w[2 * k + 1].y, avB.z, QBy);
        }

        // stage Jout partials: col0 = jo.(P.x, Qy), col1 = jo.(Qx, P.y)
        sOut[t & 7][0][lane] = make_float2(fmaf(jo.x, PA.x, jo.y * QAy),
                                           fmaf(jo.x, QAx, jo.y * PA.y));
        sOut[t & 7][1][lane] = make_float2(fmaf(jo.x, PB.x, jo.y * QBy),
                                           fmaf(jo.x, QBx, jo.y * PB.y));

        x4 = x4n;
        p ^= 1;
    }

    // final flush (steps 1016..1023)
    __syncwarp();
    if (lane < 16) {
        int g = lane >> 3, L = lane & 7;
        float2 s0 = sOut[L][g][0];
        float2 s1 = sOut[L][g][1];
        #pragma unroll
        for (int l = 2; l < KPAIR; l += 2) {
            s0 = fadd2(s0, sOut[L][g][l]);
            if (l + 1 < KPAIR) s1 = fadd2(s1, sOut[L][g][l + 1]);
        }
        *reinterpret_cast<float2*>(&out[(T_STEPS - 8 + L) * B_DIM + gc + 2 * g]) = fadd2(s0, s1);
    }
}

extern "C" void kernel_launch(void* const* d_in, const int* in_sizes, int n_in,
                              void* d_out, int out_size) {
    const float* inpt = (const float*)d_in[0];
    const float* Jin  = (const float*)d_in[1];
    const float* Jrec = (const float*)d_in[2];
    const float* Jout = (const float*)d_in[3];
    const float* bias = (const float*)d_in[4];
    const float* h0   = (const float*)d_in[5];
    float* out = (float*)d_out;

    rnn_persist<<<GRID, 32>>>(inpt, Jin, Jrec, Jout, bias, h0, out);
}